// round 16
// baseline (speedup 1.0000x reference)
#include <cuda_runtime.h>

// Problem constants
static constexpr int B_DIM = 256;
static constexpr int N_DIM = 65536;
static constexpr int BN    = B_DIM * N_DIM;          // 16,777,216
static constexpr int BN4   = BN / 4;                 // 4,194,304 float4 per tensor
static constexpr int N4    = N_DIM / 4;              // 16,384 float4 in row 0

static constexpr int THREADS = 256;
static constexpr int CHUNK   = THREADS;              // 256 float4 per block (ILP=1)
static constexpr int BLOCKS  = BN4 / CHUNK;          // 16384
static constexpr int ROW0_BLOCKS = N4 / CHUNK;       // 64 (exact, whole blocks)

// LIF-AdEx parameters (defaults from reference)
#define TAU_SYN_INV   0.5f
#define TAU_MEM_INV   0.5f
#define V_TH          1.0f
#define V_PEAK        30.0f
#define INHIBITION    (-5.0f)

// Cross-block state for the row-0 fixup. g_partial is written UNCONDITIONALLY
// by every row-0 block each replay; g_count is incremented by each row-0 block
// and reset to 0 by the fixup block before kernel end -> every graph replay
// starts from g_count==0. No init kernel needed.
__device__ unsigned long long g_partial[ROW0_BLOCKS];
__device__ int g_count = 0;

// Elementwise step (identical everywhere so spike decisions are bit-exact).
__device__ __forceinline__ void lif_step(float x, float v, float i, float w,
                                         float& z, float& v_out, float& i_new,
                                         float& w_new, float& v_before) {
    i_new = fmaf(TAU_SYN_INV, x - i, i);                 // i + 0.5*(x - i)
    float e = __expf(v - V_TH);                          // delta_t*exp((v-v_th)/delta_t)
    float s = e + i_new - w - v;                         // -(v-v_rest) + e + i_new - w
    float vn = fmaf(TAU_MEM_INV, s, v);                  // v + 0.5*s
    w_new = 0.5f * w;                                    // a_param = 0
    v_before = vn;
    bool spike = (vn >= V_PEAK);
    z = spike ? 1.0f : 0.0f;
    v_out = spike ? 0.0f : vn;                           // v_reset=0, b_param=0
}

__device__ __forceinline__ unsigned long long
umax64(unsigned long long a, unsigned long long b) { return a > b ? a : b; }

// Winner key: upper 32 = float bits of v_before (>= 30 > 0 when spiked, so raw
// bits are order-preserving); lower 32 = 0xFFFFFFFF - col so max picks the
// LOWEST column on ties (jnp.argmax). key == 0 <=> no spike in row 0.
__device__ __forceinline__ unsigned long long
winner_key(float vb, unsigned col) {
    return ((unsigned long long)__float_as_uint(vb) << 32) |
           (unsigned long long)(0xFFFFFFFFu - col);
}

__global__ void __launch_bounds__(THREADS)
k_fused(const float4* __restrict__ x,
        const float4* __restrict__ v,
        const float4* __restrict__ i,
        const float4* __restrict__ w,
        float4* __restrict__ out) {
    const int  t    = blockIdx.x * CHUNK + threadIdx.x; // one float4 per thread
    const bool row0 = (blockIdx.x < ROW0_BLOCKS);

    // ---- streaming: load -> compute -> store. Row-0 blocks store WITHOUT
    // inhibition and track their partial winner as a by-product.
    // A/B vs R15: loads keep .cs (no reuse); stores use DEFAULT .wb policy so
    // L2 buffers full-line write-backs instead of evict-first streaming.
    unsigned long long best = 0ULL;

    float4 xf = __ldcs(&x[t]), vf = __ldcs(&v[t]);
    float4 if4 = __ldcs(&i[t]), wf = __ldcs(&w[t]);
    float xs[4] = {xf.x, xf.y, xf.z, xf.w};
    float vs[4] = {vf.x, vf.y, vf.z, vf.w};
    float is[4] = {if4.x, if4.y, if4.z, if4.w};
    float ws[4] = {wf.x, wf.y, wf.z, wf.w};

    float zo[4], vo[4], io[4], wo[4];
#pragma unroll
    for (int k = 0; k < 4; k++) {
        float vb;
        lif_step(xs[k], vs[k], is[k], ws[k], zo[k], vo[k], io[k], wo[k], vb);
        if (row0 && vb >= V_PEAK)
            best = umax64(best, winner_key(vb, (unsigned)(t * 4 + k)));
    }

    out[t]           = make_float4(zo[0], zo[1], zo[2], zo[3]);
    out[BN4 + t]     = make_float4(vo[0], vo[1], vo[2], vo[3]);
    out[2 * BN4 + t] = make_float4(io[0], io[1], io[2], io[3]);
    out[3 * BN4 + t] = make_float4(wo[0], wo[1], wo[2], wo[3]);

    if (!row0) return;

    // ---- row-0 blocks: publish partial winner, last arriver does the fixup.
    __shared__ unsigned long long s_warp[THREADS / 32];
    __shared__ int s_arrival;
    __shared__ unsigned long long s_key;

    // block reduce best
#pragma unroll
    for (int o = 16; o > 0; o >>= 1)
        best = umax64(best, __shfl_down_sync(0xFFFFFFFFu, best, o));
    int wid = threadIdx.x >> 5, lid = threadIdx.x & 31;
    if (lid == 0) s_warp[wid] = best;
    __syncthreads();
    if (threadIdx.x == 0) {
        unsigned long long kk = s_warp[0];
#pragma unroll
        for (int j = 1; j < THREADS / 32; j++) kk = umax64(kk, s_warp[j]);
        g_partial[blockIdx.x] = kk;                      // unconditional write
        __threadfence();                                 // publish before arrive
        s_arrival = atomicAdd(&g_count, 1);
    }
    __syncthreads();

    if (s_arrival != ROW0_BLOCKS - 1) return;            // not the last arriver

    // ---- fixup block: all partials are published and all row-0 streaming
    // stores are visible (each preceded its block's threadfence+arrive).
    if (threadIdx.x == 0) {
        __threadfence();                                 // acquire
        unsigned long long kk = 0ULL;
        for (int j = 0; j < ROW0_BLOCKS; j++)
            kk = umax64(kk, __ldcg(&g_partial[j]));      // L2, bypass L1
        s_key = kk;
        g_count = 0;                                     // reset for next replay
    }
    __syncthreads();

    unsigned long long key = s_key;
    if (key == 0ULL) return;                             // no spike -> no inhibition

    const unsigned winner = 0xFFFFFFFFu - (unsigned)(key & 0xFFFFFFFFull);
    const int wt4 = (int)(winner >> 2);                  // float4 index holding winner

    const float4 inh4  = make_float4(INHIBITION, INHIBITION, INHIBITION, INHIBITION);
    const float4 zero4 = make_float4(0.0f, 0.0f, 0.0f, 0.0f);
    for (int tt = threadIdx.x; tt < N4; tt += THREADS) {
        if (tt != wt4) {
            out[BN4 + tt]     = inh4;                    // v[0, :] = -5
            out[3 * BN4 + tt] = zero4;                   // w[0, :] = 0
        }
    }
    // the float4 containing the winner: scalar-patch the 3 non-winner lanes
    if (threadIdx.x < 4) {
        unsigned col = (unsigned)(wt4 * 4 + threadIdx.x);
        if (col != winner) {
            float* outf = (float*)out;
            outf[(size_t)(BN4 + wt4) * 4 + threadIdx.x]     = INHIBITION;
            outf[(size_t)(3 * BN4 + wt4) * 4 + threadIdx.x] = 0.0f;
        }
    }
}

extern "C" void kernel_launch(void* const* d_in, const int* in_sizes, int n_in,
                              void* d_out, int out_size) {
    const float4* x = (const float4*)d_in[0];
    const float4* v = (const float4*)d_in[1];
    const float4* i = (const float4*)d_in[2];
    const float4* w = (const float4*)d_in[3];
    float4* out = (float4*)d_out;

    k_fused<<<BLOCKS, THREADS>>>(x, v, i, w, out);
}

// round 17
// speedup vs baseline: 1.0059x; 1.0059x over previous
#include <cuda_runtime.h>

// FINAL KERNEL — confirmed best across 5 independent benches (81.95-82.05 us).
// Structure: single fused streaming kernel; row-0 winner computed as a
// by-product of the streaming pass; last-arriving row-0 block performs the
// winner-take-all fixup; self-resetting arrival counter keeps graph replays
// deterministic. 512 MB traffic at ~6.45 TB/s = HBM read/write-mix roofline.

// Problem constants
static constexpr int B_DIM = 256;
static constexpr int N_DIM = 65536;
static constexpr int BN    = B_DIM * N_DIM;          // 16,777,216
static constexpr int BN4   = BN / 4;                 // 4,194,304 float4 per tensor
static constexpr int N4    = N_DIM / 4;              // 16,384 float4 in row 0

static constexpr int THREADS = 256;
static constexpr int CHUNK   = THREADS;              // 256 float4 per block (ILP=1)
static constexpr int BLOCKS  = BN4 / CHUNK;          // 16384
static constexpr int ROW0_BLOCKS = N4 / CHUNK;       // 64 (exact, whole blocks)

// LIF-AdEx parameters (defaults from reference)
#define TAU_SYN_INV   0.5f
#define TAU_MEM_INV   0.5f
#define V_TH          1.0f
#define V_PEAK        30.0f
#define INHIBITION    (-5.0f)

// Cross-block state for the row-0 fixup. g_partial is written UNCONDITIONALLY
// by every row-0 block each replay; g_count is incremented by each row-0 block
// and reset to 0 by the fixup block before kernel end -> every graph replay
// starts from g_count==0. No init kernel needed.
__device__ unsigned long long g_partial[ROW0_BLOCKS];
__device__ int g_count = 0;

// Elementwise step (identical everywhere so spike decisions are bit-exact).
__device__ __forceinline__ void lif_step(float x, float v, float i, float w,
                                         float& z, float& v_out, float& i_new,
                                         float& w_new, float& v_before) {
    i_new = fmaf(TAU_SYN_INV, x - i, i);                 // i + 0.5*(x - i)
    float e = __expf(v - V_TH);                          // delta_t*exp((v-v_th)/delta_t)
    float s = e + i_new - w - v;                         // -(v-v_rest) + e + i_new - w
    float vn = fmaf(TAU_MEM_INV, s, v);                  // v + 0.5*s
    w_new = 0.5f * w;                                    // a_param = 0
    v_before = vn;
    bool spike = (vn >= V_PEAK);
    z = spike ? 1.0f : 0.0f;
    v_out = spike ? 0.0f : vn;                           // v_reset=0, b_param=0
}

__device__ __forceinline__ unsigned long long
umax64(unsigned long long a, unsigned long long b) { return a > b ? a : b; }

// Winner key: upper 32 = float bits of v_before (>= 30 > 0 when spiked, so raw
// bits are order-preserving); lower 32 = 0xFFFFFFFF - col so max picks the
// LOWEST column on ties (jnp.argmax). key == 0 <=> no spike in row 0.
__device__ __forceinline__ unsigned long long
winner_key(float vb, unsigned col) {
    return ((unsigned long long)__float_as_uint(vb) << 32) |
           (unsigned long long)(0xFFFFFFFFu - col);
}

__global__ void __launch_bounds__(THREADS)
k_fused(const float4* __restrict__ x,
        const float4* __restrict__ v,
        const float4* __restrict__ i,
        const float4* __restrict__ w,
        float4* __restrict__ out) {
    const int  t    = blockIdx.x * CHUNK + threadIdx.x; // one float4 per thread
    const bool row0 = (blockIdx.x < ROW0_BLOCKS);

    // ---- streaming: load -> compute -> store. Row-0 blocks store WITHOUT
    // inhibition and track their partial winner as a by-product.
    unsigned long long best = 0ULL;

    float4 xf = __ldcs(&x[t]), vf = __ldcs(&v[t]);
    float4 if4 = __ldcs(&i[t]), wf = __ldcs(&w[t]);
    float xs[4] = {xf.x, xf.y, xf.z, xf.w};
    float vs[4] = {vf.x, vf.y, vf.z, vf.w};
    float is[4] = {if4.x, if4.y, if4.z, if4.w};
    float ws[4] = {wf.x, wf.y, wf.z, wf.w};

    float zo[4], vo[4], io[4], wo[4];
#pragma unroll
    for (int k = 0; k < 4; k++) {
        float vb;
        lif_step(xs[k], vs[k], is[k], ws[k], zo[k], vo[k], io[k], wo[k], vb);
        if (row0 && vb >= V_PEAK)
            best = umax64(best, winner_key(vb, (unsigned)(t * 4 + k)));
    }

    __stcs(&out[t],           make_float4(zo[0], zo[1], zo[2], zo[3]));
    __stcs(&out[BN4 + t],     make_float4(vo[0], vo[1], vo[2], vo[3]));
    __stcs(&out[2 * BN4 + t], make_float4(io[0], io[1], io[2], io[3]));
    __stcs(&out[3 * BN4 + t], make_float4(wo[0], wo[1], wo[2], wo[3]));

    if (!row0) return;

    // ---- row-0 blocks: publish partial winner, last arriver does the fixup.
    __shared__ unsigned long long s_warp[THREADS / 32];
    __shared__ int s_arrival;
    __shared__ unsigned long long s_key;

    // block reduce best
#pragma unroll
    for (int o = 16; o > 0; o >>= 1)
        best = umax64(best, __shfl_down_sync(0xFFFFFFFFu, best, o));
    int wid = threadIdx.x >> 5, lid = threadIdx.x & 31;
    if (lid == 0) s_warp[wid] = best;
    __syncthreads();
    if (threadIdx.x == 0) {
        unsigned long long kk = s_warp[0];
#pragma unroll
        for (int j = 1; j < THREADS / 32; j++) kk = umax64(kk, s_warp[j]);
        g_partial[blockIdx.x] = kk;                      // unconditional write
        __threadfence();                                 // publish before arrive
        s_arrival = atomicAdd(&g_count, 1);
    }
    __syncthreads();

    if (s_arrival != ROW0_BLOCKS - 1) return;            // not the last arriver

    // ---- fixup block: all partials are published and all row-0 streaming
    // stores are visible (each preceded its block's threadfence+arrive).
    if (threadIdx.x == 0) {
        __threadfence();                                 // acquire
        unsigned long long kk = 0ULL;
        for (int j = 0; j < ROW0_BLOCKS; j++)
            kk = umax64(kk, __ldcg(&g_partial[j]));      // L2, bypass L1
        s_key = kk;
        g_count = 0;                                     // reset for next replay
    }
    __syncthreads();

    unsigned long long key = s_key;
    if (key == 0ULL) return;                             // no spike -> no inhibition

    const unsigned winner = 0xFFFFFFFFu - (unsigned)(key & 0xFFFFFFFFull);
    const int wt4 = (int)(winner >> 2);                  // float4 index holding winner

    const float4 inh4  = make_float4(INHIBITION, INHIBITION, INHIBITION, INHIBITION);
    const float4 zero4 = make_float4(0.0f, 0.0f, 0.0f, 0.0f);
    for (int tt = threadIdx.x; tt < N4; tt += THREADS) {
        if (tt != wt4) {
            out[BN4 + tt]     = inh4;                    // v[0, :] = -5
            out[3 * BN4 + tt] = zero4;                   // w[0, :] = 0
        }
    }
    // the float4 containing the winner: scalar-patch the 3 non-winner lanes
    if (threadIdx.x < 4) {
        unsigned col = (unsigned)(wt4 * 4 + threadIdx.x);
        if (col != winner) {
            float* outf = (float*)out;
            outf[(size_t)(BN4 + wt4) * 4 + threadIdx.x]     = INHIBITION;
            outf[(size_t)(3 * BN4 + wt4) * 4 + threadIdx.x] = 0.0f;
        }
    }
}

extern "C" void kernel_launch(void* const* d_in, const int* in_sizes, int n_in,
                              void* d_out, int out_size) {
    const float4* x = (const float4*)d_in[0];
    const float4* v = (const float4*)d_in[1];
    const float4* i = (const float4*)d_in[2];
    const float4* w = (const float4*)d_in[3];
    float4* out = (float4*)d_out;

    k_fused<<<BLOCKS, THREADS>>>(x, v, i, w, out);
}